// round 2
// baseline (speedup 1.0000x reference)
#include <cuda_runtime.h>
#include <math.h>

// Problem constants (fixed shapes)
#define NN 100000
#define NE 1600000
#define FDIM 64
#define F3 32

// ---------------- scratch (static __device__, no allocation) ----------------
__device__ float g_h0[NN * FDIM];       // layer output ping
__device__ float g_h1[NN * FDIM];       // layer output pong
__device__ float g_agg[NN * FDIM];      // aggregated features
__device__ int   g_deg[NN];
__device__ int   g_rowptr[NN + 1];
__device__ int   g_cursor[NN];
__device__ int   g_col[NE];
__device__ int   g_is64;
__device__ float g_meansum[F3];
__device__ float g_ctx[F3];
__device__ float g_pooled[F3];

// ---------------- edge dtype detection ----------------
// If buffer is int64 (values < 1e5, nonnegative), every odd 32-bit word of the
// first 2048 entries is 0. If int32, those words are random node ids (all-zero
// probability ~ (1e-5)^2048).
__global__ void __launch_bounds__(256) k_detect(const void* e) {
    const unsigned* w = (const unsigned*)e;
    __shared__ int any;
    if (threadIdx.x == 0) any = 0;
    __syncthreads();
    int local = 0;
    for (int i = threadIdx.x; i < 2048; i += blockDim.x)
        if (w[2 * i + 1] != 0u) local = 1;
    if (local) atomicOr(&any, 1);
    __syncthreads();
    if (threadIdx.x == 0) g_is64 = any ? 0 : 1;
}

__device__ __forceinline__ int edge_at(const void* e, int idx) {
    if (g_is64) return (int)((const long long*)e)[idx];
    return ((const int*)e)[idx];
}

// ---------------- zero scratch ----------------
__global__ void __launch_bounds__(256) k_zero() {
    int i = blockIdx.x * blockDim.x + threadIdx.x;
    if (i < NN) g_deg[i] = 0;
    if (i < F3) { g_meansum[i] = 0.f; g_pooled[i] = 0.f; }
}

// ---------------- CSR build ----------------
__global__ void __launch_bounds__(256) k_count(const void* e) {
    int i = blockIdx.x * blockDim.x + threadIdx.x;
    if (i < NE) {
        int t = edge_at(e, NE + i);
        atomicAdd(&g_deg[t], 1);
    }
}

// single-block scan: 1024 threads, ~98 elements each
__global__ void __launch_bounds__(1024, 1) k_scan() {
    __shared__ int part[1024];
    const int tid = threadIdx.x;
    const int CH = (NN + 1023) / 1024;
    const int base = tid * CH;
    int s = 0;
    for (int j = 0; j < CH; j++) {
        int idx = base + j;
        if (idx < NN) s += g_deg[idx];
    }
    part[tid] = s;
    __syncthreads();
    // inclusive Hillis-Steele scan over 1024 partials
    for (int off = 1; off < 1024; off <<= 1) {
        int v = (tid >= off) ? part[tid - off] : 0;
        __syncthreads();
        part[tid] += v;
        __syncthreads();
    }
    int run = (tid == 0) ? 0 : part[tid - 1];
    for (int j = 0; j < CH; j++) {
        int idx = base + j;
        if (idx < NN) { g_rowptr[idx] = run; run += g_deg[idx]; }
    }
    if (tid == 1023) g_rowptr[NN] = part[1023];
}

__global__ void __launch_bounds__(256) k_initcursor() {
    int i = blockIdx.x * blockDim.x + threadIdx.x;
    if (i < NN) g_cursor[i] = g_rowptr[i];
}

__global__ void __launch_bounds__(256) k_fill(const void* e) {
    int i = blockIdx.x * blockDim.x + threadIdx.x;
    if (i < NE) {
        int s = edge_at(e, i);
        int t = edge_at(e, NE + i);
        int pos = atomicAdd(&g_cursor[t], 1);
        g_col[pos] = s;
    }
}

// ---------------- mean aggregation (warp per target node, F=64) ----------------
__global__ void __launch_bounds__(256) k_aggregate(const float* __restrict__ x) {
    int warp = (blockIdx.x * blockDim.x + threadIdx.x) >> 5;
    int lane = threadIdx.x & 31;
    if (warp >= NN) return;
    int beg = g_rowptr[warp], end = g_rowptr[warp + 1];
    const float2* __restrict__ x2 = (const float2*)x;
    float2 acc = make_float2(0.f, 0.f);
    for (int e = beg; e < end; e++) {
        int s = g_col[e];
        float2 v = __ldg(&x2[s * 32 + lane]);
        acc.x += v.x; acc.y += v.y;
    }
    float inv = 1.0f / fmaxf((float)(end - beg), 1.0f);
    acc.x *= inv; acc.y *= inv;
    ((float2*)g_agg)[warp * 32 + lane] = acc;
}

// ---------------- fused linear: out = agg@Wl + b + x@Wr ----------------
// Block = 256 threads, 32-node tile. Weights staged in shared once per block.
template <int FIN, int FOUT>
__global__ void __launch_bounds__(256) k_linear(
    const float* __restrict__ x, const float* __restrict__ agg,
    const float* __restrict__ Wl, const float* __restrict__ b,
    const float* __restrict__ Wr, float* __restrict__ out)
{
    __shared__ float sWl[FIN * FOUT];
    __shared__ float sWr[FIN * FOUT];
    __shared__ float sA[32][FIN];
    __shared__ float sX[32][FIN];

    const int tid = threadIdx.x;
    // stage weights (float4)
    const float4* Wl4 = (const float4*)Wl;
    const float4* Wr4 = (const float4*)Wr;
    for (int i = tid; i < FIN * FOUT / 4; i += 256) {
        ((float4*)sWl)[i] = Wl4[i];
        ((float4*)sWr)[i] = Wr4[i];
    }
    const int tile0 = blockIdx.x * 32;
    // stage node tiles
    const float4* A4 = (const float4*)(agg + tile0 * FIN);
    const float4* X4 = (const float4*)(x + tile0 * FIN);
    for (int i = tid; i < 32 * FIN / 4; i += 256) {
        ((float4*)&sA[0][0])[i] = A4[i];
        ((float4*)&sX[0][0])[i] = X4[i];
    }
    __syncthreads();

    const int col = tid % FOUT;
    const int grp = tid / FOUT;
    const int GROUPS = 256 / FOUT;
    const int TM = 32 / GROUPS;

    float acc[TM];
    float bias = __ldg(&b[col]);
#pragma unroll
    for (int m = 0; m < TM; m++) acc[m] = bias;

#pragma unroll
    for (int k = 0; k < FIN; k++) {
        float wl = sWl[k * FOUT + col];
        float wr = sWr[k * FOUT + col];
#pragma unroll
        for (int m = 0; m < TM; m++) {
            int node = grp * TM + m;
            acc[m] += sA[node][k] * wl + sX[node][k] * wr;
        }
    }
#pragma unroll
    for (int m = 0; m < TM; m++) {
        int node = tile0 + grp * TM + m;
        out[node * FOUT + col] = acc[m];
    }
}

// ---------------- row L2-normalize (+optional relu); warp per node ----------------
template <int F, bool RELU>
__global__ void __launch_bounds__(256) k_norm(float* __restrict__ h) {
    int warp = (blockIdx.x * blockDim.x + threadIdx.x) >> 5;
    int lane = threadIdx.x & 31;
    if (warp >= NN) return;
    float* row = h + warp * F;
    float v0 = row[lane];
    float v1 = (F == 64) ? row[lane + 32] : 0.f;
    float ss = v0 * v0 + v1 * v1;
#pragma unroll
    for (int o = 16; o > 0; o >>= 1) ss += __shfl_xor_sync(0xffffffffu, ss, o);
    float inv = 1.0f / fmaxf(sqrtf(ss), 1e-12f);
    v0 *= inv; v1 *= inv;
    if (RELU) { v0 = fmaxf(v0, 0.f); v1 = fmaxf(v1, 0.f); }
    row[lane] = v0;
    if (F == 64) row[lane + 32] = v1;
}

// ---------------- pooling ----------------
__global__ void __launch_bounds__(256) k_meansum(const float* __restrict__ h) {
    __shared__ float part[F3];
    if (threadIdx.x < F3) part[threadIdx.x] = 0.f;
    __syncthreads();
    int lane = threadIdx.x & 31;
    int wid = (blockIdx.x * blockDim.x + threadIdx.x) >> 5;
    int nw = (gridDim.x * blockDim.x) >> 5;
    float acc = 0.f;
    for (int n = wid; n < NN; n += nw) acc += h[n * F3 + lane];
    atomicAdd(&part[lane], acc);
    __syncthreads();
    if (threadIdx.x < F3) atomicAdd(&g_meansum[threadIdx.x], part[threadIdx.x]);
}

__global__ void __launch_bounds__(32) k_context(const float* __restrict__ Watt) {
    int j = threadIdx.x;  // 32 threads
    float s = 0.f;
    const float invN = 1.0f / (float)NN;
    for (int k = 0; k < F3; k++) s += (g_meansum[k] * invN) * Watt[k * F3 + j];
    g_ctx[j] = tanhf(s);
}

__global__ void __launch_bounds__(256) k_pool(const float* __restrict__ h) {
    __shared__ float part[F3];
    if (threadIdx.x < F3) part[threadIdx.x] = 0.f;
    __syncthreads();
    int lane = threadIdx.x & 31;
    float ctx = g_ctx[lane];
    int wid = (blockIdx.x * blockDim.x + threadIdx.x) >> 5;
    int nw = (gridDim.x * blockDim.x) >> 5;
    float acc = 0.f;
    for (int n = wid; n < NN; n += nw) {
        float v = h[n * F3 + lane];
        float d = v * ctx;
#pragma unroll
        for (int o = 16; o > 0; o >>= 1) d += __shfl_xor_sync(0xffffffffu, d, o);
        float att = 1.0f / (1.0f + expf(-d));
        acc += att * v;
    }
    atomicAdd(&part[lane], acc);
    __syncthreads();
    if (threadIdx.x < F3) atomicAdd(&g_pooled[threadIdx.x], part[threadIdx.x]);
}

__global__ void __launch_bounds__(32) k_final(const float* __restrict__ Wfc, const float* __restrict__ bfc,
                        const float* __restrict__ Ws, const float* __restrict__ bs,
                        float* __restrict__ out) {
    __shared__ float hid[16];
    int t = threadIdx.x;  // 32 threads
    if (t < 16) {
        float s = bfc[t];
        for (int j = 0; j < F3; j++) s += g_pooled[j] * Wfc[j * 16 + t];
        hid[t] = fmaxf(s, 0.f);
    }
    __syncthreads();
    if (t == 0) {
        float s = bs[0];
        for (int k = 0; k < 16; k++) s += hid[k] * Ws[k];
        out[0] = 1.0f / (1.0f + expf(-s));
    }
}

// ---------------- launch ----------------
extern "C" void kernel_launch(void* const* d_in, const int* in_sizes, int n_in,
                              void* d_out, int out_size) {
    const float* feats = (const float*)d_in[0];
    const void*  edges = d_in[1];
    const float* W1l = (const float*)d_in[2];
    const float* b1  = (const float*)d_in[3];
    const float* W1r = (const float*)d_in[4];
    const float* W2l = (const float*)d_in[5];
    const float* b2  = (const float*)d_in[6];
    const float* W2r = (const float*)d_in[7];
    const float* W3l = (const float*)d_in[8];
    const float* b3  = (const float*)d_in[9];
    const float* W3r = (const float*)d_in[10];
    const float* Watt= (const float*)d_in[11];
    const float* Wfc = (const float*)d_in[12];
    const float* bfc = (const float*)d_in[13];
    const float* Ws  = (const float*)d_in[14];
    const float* bs  = (const float*)d_in[15];
    float* out = (float*)d_out;

    const int TB = 256;
    const int gN = (NN + TB - 1) / TB;        // 391
    const int gE = (NE + TB - 1) / TB;        // 6250
    const int gWarpN = (NN * 32 + TB - 1) / TB; // 12500 (warp per node)
    const int gTile = NN / 32;                // 3125 (exact)

    // edge dtype + CSR build (once, reused by all 3 layers)
    k_detect<<<1, 256>>>(edges);
    k_zero<<<gN, TB>>>();
    k_count<<<gE, TB>>>(edges);
    k_scan<<<1, 1024>>>();
    k_initcursor<<<gN, TB>>>();
    k_fill<<<gE, TB>>>(edges);

    // layer 1: feats -> g_h0
    k_aggregate<<<gWarpN, TB>>>(feats);
    k_linear<64, 64><<<gTile, TB>>>(feats, g_agg, W1l, b1, W1r, g_h0);
    k_norm<64, true><<<gWarpN, TB>>>(g_h0);

    // layer 2: g_h0 -> g_h1
    k_aggregate<<<gWarpN, TB>>>(g_h0);
    k_linear<64, 64><<<gTile, TB>>>(g_h0, g_agg, W2l, b2, W2r, g_h1);
    k_norm<64, true><<<gWarpN, TB>>>(g_h1);

    // layer 3: g_h1 -> g_h0 (first N*32 floats)
    k_aggregate<<<gWarpN, TB>>>(g_h1);
    k_linear<64, 32><<<gTile, TB>>>(g_h1, g_agg, W3l, b3, W3r, g_h0);
    k_norm<32, false><<<gWarpN, TB>>>(g_h0);

    // SimGNN attention pooling + MLP head
    k_meansum<<<592, TB>>>(g_h0);
    k_context<<<1, 32>>>(Watt);
    k_pool<<<592, TB>>>(g_h0);
    k_final<<<1, 32>>>(Wfc, bfc, Ws, bs, out);
}

// round 3
// speedup vs baseline: 1.1933x; 1.1933x over previous
#include <cuda_runtime.h>
#include <math.h>

#define NN 100000
#define NE 1600000
#define F3 32

// ---------------- scratch ----------------
__device__ float g_h0[NN * 64];
__device__ float g_h1[NN * 64];
__device__ int   g_deg[NN];
__device__ int   g_start[NN];
__device__ int   g_cursor[NN];
__device__ int   g_col[NE];
__device__ int   g_tgt[NE];
__device__ int   g_total;
__device__ int   g_is64;
__device__ float g_meansum[F3];
__device__ float g_ctx[F3];
__device__ float g_pooled[F3];

// ---------------- edge dtype detection ----------------
__global__ void __launch_bounds__(256) k_detect(const void* e) {
    const unsigned* w = (const unsigned*)e;
    __shared__ int any;
    if (threadIdx.x == 0) any = 0;
    __syncthreads();
    int local = 0;
    for (int i = threadIdx.x; i < 2048; i += blockDim.x)
        if (w[2 * i + 1] != 0u) local = 1;
    if (local) atomicOr(&any, 1);
    __syncthreads();
    if (threadIdx.x == 0) g_is64 = any ? 0 : 1;
}

__device__ __forceinline__ int edge_at(const void* e, int idx) {
    if (g_is64) return (int)((const long long*)e)[idx];
    return ((const int*)e)[idx];
}

__global__ void __launch_bounds__(256) k_zero() {
    int i = blockIdx.x * blockDim.x + threadIdx.x;
    if (i < NN) g_deg[i] = 0;
    if (i < F3) { g_meansum[i] = 0.f; g_pooled[i] = 0.f; }
    if (i == 0) g_total = 0;
}

// ---------------- prep: convert edges to int32 + count degrees ----------------
__global__ void __launch_bounds__(256) k_prep(const void* e) {
    int i = blockIdx.x * blockDim.x + threadIdx.x;
    if (i < NE) {
        int s = edge_at(e, i);
        int t = edge_at(e, NE + i);
        g_col[i] = s;          // temporarily store src here (re-permuted by k_fill)
        g_tgt[i] = t;
        atomicAdd(&g_deg[t], 1);
    }
}

// ---------------- order-free offset allocation (one atomic per block) ----------------
__global__ void __launch_bounds__(256) k_offsets() {
    const int tid = threadIdx.x;
    const int lane = tid & 31;
    const int wid = tid >> 5;
    int i = blockIdx.x * 256 + tid;
    int d = (i < NN) ? g_deg[i] : 0;
    // warp inclusive scan
    int p = d;
#pragma unroll
    for (int o = 1; o < 32; o <<= 1) {
        int v = __shfl_up_sync(0xffffffffu, p, o);
        if (lane >= o) p += v;
    }
    __shared__ int wsum[8];
    __shared__ int blockbase;
    if (lane == 31) wsum[wid] = p;
    __syncthreads();
    if (tid < 8) {
        int v = wsum[tid];
#pragma unroll
        for (int o = 1; o < 8; o <<= 1) {
            int u = __shfl_up_sync(0xffu, v, o);
            if (tid >= o) v += u;
        }
        wsum[tid] = v;
        if (tid == 7) blockbase = atomicAdd(&g_total, v);
    }
    __syncthreads();
    int base = blockbase + (wid ? wsum[wid - 1] : 0) + p - d;
    if (i < NN) { g_start[i] = base; g_cursor[i] = base; }
}

// ---------------- fill: permute src into CSR slots ----------------
// reads src from g_col[i] (linear), writes into g_col[pos]. To avoid
// read/write hazard on same array, stage src in registers via separate pass:
// we instead use g_tgt for target and keep src in a second scratch.
__device__ int g_srctmp[NE];
__global__ void __launch_bounds__(256) k_copytmp() {
    int i = blockIdx.x * blockDim.x + threadIdx.x;
    if (i < NE) g_srctmp[i] = g_col[i];
}
__global__ void __launch_bounds__(256) k_fill() {
    int i = blockIdx.x * blockDim.x + threadIdx.x;
    if (i < NE) {
        int t = g_tgt[i];
        int pos = atomicAdd(&g_cursor[t], 1);
        g_col[pos] = g_srctmp[i];
    }
}

// ---------------- fused layer: aggregate + dual GEMM + L2norm (+relu) ----------------
// FIN = 64 always. Block = 256 threads handles a 32-node tile.
template <int FOUT, bool RELU>
__global__ void __launch_bounds__(256) k_layer(
    const float* __restrict__ x,
    const float* __restrict__ Wl, const float* __restrict__ b,
    const float* __restrict__ Wr, float* __restrict__ out)
{
    __shared__ float sWl[64 * FOUT];
    __shared__ float sWr[64 * FOUT];
    __shared__ float sX[32][64];
    __shared__ float sA[32][64];
    __shared__ float sO[32][FOUT];

    const int tid = threadIdx.x;
    const int lane = tid & 31;
    const int wid = tid >> 5;
    const int tile0 = blockIdx.x * 32;

    // stage weights + x tile (float4)
    {
        const float4* Wl4 = (const float4*)Wl;
        const float4* Wr4 = (const float4*)Wr;
        for (int i = tid; i < 64 * FOUT / 4; i += 256) {
            ((float4*)sWl)[i] = Wl4[i];
            ((float4*)sWr)[i] = Wr4[i];
        }
        const float4* X4 = (const float4*)(x + tile0 * 64);
        for (int i = tid; i < 32 * 64 / 4; i += 256)
            ((float4*)&sX[0][0])[i] = X4[i];
    }

    // aggregate: each warp owns 4 nodes of the tile
    const float2* __restrict__ x2 = (const float2*)x;
#pragma unroll
    for (int j = 0; j < 4; j++) {
        int nl = wid * 4 + j;
        int n = tile0 + nl;
        int beg = g_start[n];
        int d = g_deg[n];
        int end = beg + d;
        float2 acc = make_float2(0.f, 0.f);
        int e = beg;
        for (; e + 4 <= end; e += 4) {
            int s0 = g_col[e], s1 = g_col[e + 1], s2 = g_col[e + 2], s3 = g_col[e + 3];
            float2 v0 = __ldg(&x2[s0 * 32 + lane]);
            float2 v1 = __ldg(&x2[s1 * 32 + lane]);
            float2 v2 = __ldg(&x2[s2 * 32 + lane]);
            float2 v3 = __ldg(&x2[s3 * 32 + lane]);
            acc.x += v0.x + v1.x + v2.x + v3.x;
            acc.y += v0.y + v1.y + v2.y + v3.y;
        }
        for (; e < end; e++) {
            int s = g_col[e];
            float2 v = __ldg(&x2[s * 32 + lane]);
            acc.x += v.x; acc.y += v.y;
        }
        float inv = 1.0f / fmaxf((float)d, 1.0f);
        acc.x *= inv; acc.y *= inv;
        ((float2*)&sA[nl][0])[lane] = acc;
    }
    __syncthreads();

    // dual GEMM: out = agg@Wl + b + x@Wr
    {
        const int col = tid % FOUT;
        const int grp = tid / FOUT;
        const int GROUPS = 256 / FOUT;
        const int TM = 32 / GROUPS;
        float acc[TM];
        float bias = __ldg(&b[col]);
#pragma unroll
        for (int m = 0; m < TM; m++) acc[m] = bias;
#pragma unroll
        for (int k = 0; k < 64; k++) {
            float wl = sWl[k * FOUT + col];
            float wr = sWr[k * FOUT + col];
#pragma unroll
            for (int m = 0; m < TM; m++) {
                int node = grp * TM + m;
                acc[m] += sA[node][k] * wl + sX[node][k] * wr;
            }
        }
#pragma unroll
        for (int m = 0; m < TM; m++)
            sO[grp * TM + m][col] = acc[m];
    }
    __syncthreads();

    // L2 normalize (+relu), warp per 4 nodes, coalesced global store
#pragma unroll
    for (int j = 0; j < 4; j++) {
        int nl = wid * 4 + j;
        float v0 = sO[nl][lane];
        float v1 = (FOUT == 64) ? sO[nl][lane + 32] : 0.f;
        float ss = v0 * v0 + v1 * v1;
#pragma unroll
        for (int o = 16; o > 0; o >>= 1) ss += __shfl_xor_sync(0xffffffffu, ss, o);
        float inv = 1.0f / fmaxf(sqrtf(ss), 1e-12f);
        v0 *= inv; v1 *= inv;
        if (RELU) { v0 = fmaxf(v0, 0.f); v1 = fmaxf(v1, 0.f); }
        float* row = out + (tile0 + nl) * FOUT;
        row[lane] = v0;
        if (FOUT == 64) row[lane + 32] = v1;
    }
}

// ---------------- pooling ----------------
__global__ void __launch_bounds__(256) k_meansum(const float* __restrict__ h) {
    __shared__ float part[F3];
    if (threadIdx.x < F3) part[threadIdx.x] = 0.f;
    __syncthreads();
    int lane = threadIdx.x & 31;
    int wid = (blockIdx.x * blockDim.x + threadIdx.x) >> 5;
    int nw = (gridDim.x * blockDim.x) >> 5;
    float acc = 0.f;
    for (int n = wid; n < NN; n += nw) acc += h[n * F3 + lane];
    atomicAdd(&part[lane], acc);
    __syncthreads();
    if (threadIdx.x < F3) atomicAdd(&g_meansum[threadIdx.x], part[threadIdx.x]);
}

__global__ void __launch_bounds__(32) k_context(const float* __restrict__ Watt) {
    int j = threadIdx.x;
    float s = 0.f;
    const float invN = 1.0f / (float)NN;
    for (int k = 0; k < F3; k++) s += (g_meansum[k] * invN) * Watt[k * F3 + j];
    g_ctx[j] = tanhf(s);
}

__global__ void __launch_bounds__(256) k_pool(const float* __restrict__ h) {
    __shared__ float part[F3];
    if (threadIdx.x < F3) part[threadIdx.x] = 0.f;
    __syncthreads();
    int lane = threadIdx.x & 31;
    float ctx = g_ctx[lane];
    int wid = (blockIdx.x * blockDim.x + threadIdx.x) >> 5;
    int nw = (gridDim.x * blockDim.x) >> 5;
    float acc = 0.f;
    for (int n = wid; n < NN; n += nw) {
        float v = h[n * F3 + lane];
        float d = v * ctx;
#pragma unroll
        for (int o = 16; o > 0; o >>= 1) d += __shfl_xor_sync(0xffffffffu, d, o);
        float att = 1.0f / (1.0f + expf(-d));
        acc += att * v;
    }
    atomicAdd(&part[lane], acc);
    __syncthreads();
    if (threadIdx.x < F3) atomicAdd(&g_pooled[threadIdx.x], part[threadIdx.x]);
}

__global__ void __launch_bounds__(32) k_final(const float* __restrict__ Wfc, const float* __restrict__ bfc,
                        const float* __restrict__ Ws, const float* __restrict__ bs,
                        float* __restrict__ out) {
    __shared__ float hid[16];
    int t = threadIdx.x;
    if (t < 16) {
        float s = bfc[t];
        for (int j = 0; j < F3; j++) s += g_pooled[j] * Wfc[j * 16 + t];
        hid[t] = fmaxf(s, 0.f);
    }
    __syncthreads();
    if (t == 0) {
        float s = bs[0];
        for (int k = 0; k < 16; k++) s += hid[k] * Ws[k];
        out[0] = 1.0f / (1.0f + expf(-s));
    }
}

// ---------------- launch ----------------
extern "C" void kernel_launch(void* const* d_in, const int* in_sizes, int n_in,
                              void* d_out, int out_size) {
    const float* feats = (const float*)d_in[0];
    const void*  edges = d_in[1];
    const float* W1l = (const float*)d_in[2];
    const float* b1  = (const float*)d_in[3];
    const float* W1r = (const float*)d_in[4];
    const float* W2l = (const float*)d_in[5];
    const float* b2  = (const float*)d_in[6];
    const float* W2r = (const float*)d_in[7];
    const float* W3l = (const float*)d_in[8];
    const float* b3  = (const float*)d_in[9];
    const float* W3r = (const float*)d_in[10];
    const float* Watt= (const float*)d_in[11];
    const float* Wfc = (const float*)d_in[12];
    const float* bfc = (const float*)d_in[13];
    const float* Ws  = (const float*)d_in[14];
    const float* bs  = (const float*)d_in[15];
    float* out = (float*)d_out;

    const int TB = 256;
    const int gN = (NN + TB - 1) / TB;
    const int gE = (NE + TB - 1) / TB;
    const int gTile = NN / 32;   // 3125

    k_detect<<<1, 256>>>(edges);
    k_zero<<<gN, TB>>>();
    k_prep<<<gE, TB>>>(edges);
    k_offsets<<<gN, TB>>>();
    k_copytmp<<<gE, TB>>>();
    k_fill<<<gE, TB>>>();

    k_layer<64, true ><<<gTile, TB>>>(feats, W1l, b1, W1r, g_h0);
    k_layer<64, true ><<<gTile, TB>>>(g_h0,  W2l, b2, W2r, g_h1);
    k_layer<32, false><<<gTile, TB>>>(g_h1,  W3l, b3, W3r, g_h0);

    k_meansum<<<592, TB>>>(g_h0);
    k_context<<<1, 32>>>(Watt);
    k_pool<<<592, TB>>>(g_h0);
    k_final<<<1, 32>>>(Wfc, bfc, Ws, bs, out);
}